// round 13
// baseline (speedup 1.0000x reference)
#include <cuda_runtime.h>
#include <cstdint>

// VectorQuantize: H=1, N=32768, D=256, K=4096.
// Round 13: R12 dual-pipe screen (best, 455.7us) + rescore/gather FUSED into
//           the screen epilogue (candidates via smem; no g_cand round-trip,
//           no separate rescore launch). Numerics identical.

#define N_TOK 32768
#define DIM   256
#define KCODE 4096
#define BM    128
#define NKT   (KCODE / 128)       // 32 k-tiles of 128 codes

#define NC_T  5                   // IMMA chunks (dims 0..159)
#define NG    6                   // dp4a groups of 16 dims (dims 160..255)
#define XW_STRIDE 28              // dp4a A row stride in words (conflict-free)
#define SA_WORDS  (8 * NC_T * 32 * 4)       // 5120
#define XW_WORDS  (BM * XW_STRIDE)          // 3584
#define CAND_WORDS (BM * 64 * 2)            // 16384 (int2 per candidate)
#define SMEM_TOTAL ((SA_WORDS + XW_WORDS + CAND_WORDS) * 4)

__device__ float    g_e2[KCODE];               // exact fp32 ||e||^2 (rescore)
__device__ int      g_e2s[KCODE];              // int ||q_e||^2 (screen)
__device__ uint32_t g_e8[512 * 8 * 32 * 2];    // IMMA B frags [nt][c][lane][hk]
__device__ uint32_t g_ebd[KCODE * 24];         // dp4a B [col][24 words]

// ---------------------------------------------------------------------------
__device__ __forceinline__ void imma16832(int c[4], uint32_t a0, uint32_t a1,
                                          uint32_t a2, uint32_t a3,
                                          uint32_t b0, uint32_t b1) {
    asm volatile(
        "mma.sync.aligned.m16n8k32.row.col.s32.s8.s8.s32 "
        "{%0,%1,%2,%3}, {%4,%5,%6,%7}, {%8,%9}, {%0,%1,%2,%3};"
        : "+r"(c[0]), "+r"(c[1]), "+r"(c[2]), "+r"(c[3])
        : "r"(a0), "r"(a1), "r"(a2), "r"(a3), "r"(b0), "r"(b1));
}
__device__ __forceinline__ int q8(float v) {
    int q = __float2int_rn(v * 32.0f);
    return max(-127, min(127, q));
}
__device__ __forceinline__ uint32_t pack4(int q0, int q1, int q2, int q3) {
    return (uint32_t)(q0 & 0xFF) | ((uint32_t)(q1 & 0xFF) << 8) |
           ((uint32_t)(q2 & 0xFF) << 16) | ((uint32_t)(q3 & 0xFF) << 24);
}

// ---------------------------------------------------------------------------
// equant: embed -> IMMA fragments (dims<160) + dp4a words (dims>=160) + e2s/e2.
// ---------------------------------------------------------------------------
__global__ void equant_kernel(const float* __restrict__ embed) {
    const int n    = (blockIdx.x * blockDim.x + threadIdx.x) >> 5;
    const int lane = threadIdx.x & 31;
    if (n >= KCODE) return;
    const float* row = embed + (size_t)n * DIM;

    float4 va = *(const float4*)(row + lane * 8);
    float4 vb = *(const float4*)(row + lane * 8 + 4);
    int   qa[8] = {q8(va.x), q8(va.y), q8(va.z), q8(va.w),
                   q8(vb.x), q8(vb.y), q8(vb.z), q8(vb.w)};
    float fv[8] = {va.x, va.y, va.z, va.w, vb.x, vb.y, vb.z, vb.w};

    int s2i = 0; float s2f = 0.f;
#pragma unroll
    for (int i = 0; i < 8; i++) { s2i += qa[i] * qa[i]; s2f = fmaf(fv[i], fv[i], s2f); }
#pragma unroll
    for (int o = 16; o > 0; o >>= 1) {
        s2i += __shfl_xor_sync(0xffffffffu, s2i, o);
        s2f += __shfl_xor_sync(0xffffffffu, s2f, o);
    }
    if (lane == 0) { g_e2s[n] = s2i; g_e2[n] = s2f; }

    const int nt = n >> 3, gidn = n & 7;
#pragma unroll
    for (int u = 0; u < 2; u++) {
        uint32_t w = pack4(qa[4 * u], qa[4 * u + 1], qa[4 * u + 2], qa[4 * u + 3]);
        int k0 = lane * 8 + 4 * u;
        if (k0 < 160) {                 // IMMA fragment region (c = 0..4)
            int c = k0 >> 5, hk = (k0 >> 4) & 1, tg = (k0 >> 2) & 3;
            g_e8[(((nt * 8 + c) * 32 + gidn * 4 + tg) << 1) + hk] = w;
        } else {                        // dp4a word region
            g_ebd[n * 24 + ((k0 - 160) >> 2)] = w;
        }
    }
}

// ---------------------------------------------------------------------------
// Screen + fused rescore/gather.
// 512 threads = 16 warps = 2 wm (64 rows) x 8 wn (16 cols of k-tile).
// Mainloop identical to R12. Epilogue: candidates -> smem, barrier, warp w
// rescoring rows 8w..8w+7 exactly as the old rescore_kernel, write winners.
// ---------------------------------------------------------------------------
__global__ __launch_bounds__(512)
void screen_kernel(const float* __restrict__ x, const float* __restrict__ embed,
                   float* __restrict__ out) {
    extern __shared__ uint32_t sm[];
    uint32_t* sA = sm;                          // SA_WORDS
    uint32_t* xw = sm + SA_WORDS;               // XW_WORDS (stride 28)
    int2*     scand = (int2*)(sm + SA_WORDS + XW_WORDS);   // [BM][64]

    const int t = threadIdx.x, lane = t & 31, w = t >> 5;
    const int wm = w & 1, wn = w >> 1;
    const int gid = lane >> 2, tig = lane & 3;
    const int n0 = blockIdx.x * BM;

    // ---- stage A: IMMA fragments (dims<160) + dp4a words (dims>=160) ----
#pragma unroll
    for (int i = 0; i < 16; i++) {
        int wid = t + 512 * i;            // 8192 words = 128 rows x 64 words
        int row = wid >> 6, wk = wid & 63, k0 = wk * 4;
        float4 v = *(const float4*)(x + (size_t)(n0 + row) * DIM + k0);
        uint32_t pw = pack4(q8(v.x), q8(v.y), q8(v.z), q8(v.w));
        if (k0 < 160) {
            int mt = row >> 4, gr = row & 7, jr = (row >> 3) & 1;
            int c = k0 >> 5, hk = (k0 >> 4) & 1, tg = (k0 >> 2) & 3;
            sA[(((mt * NC_T + c) * 32 + gr * 4 + tg) << 2) + jr + 2 * hk] = pw;
        } else {
            xw[row * XW_STRIDE + (wk - 40)] = pw;
        }
    }
    __syncthreads();

    const int cloc0 = wn * 16 + tig * 2;
    const uint4* __restrict__ gb = (const uint4*)g_ebd;   // [col][6] uint4
    const uint2* __restrict__ gi = (const uint2*)g_e8;    // [nt*8+c][32] uint2

    uint32_t t2a[8], t2b[8];
#pragma unroll
    for (int s = 0; s < 8; s++) { t2a[s] = 0xFFFFFFFFu; t2b[s] = 0xFFFFFFFFu; }

    // prologue: prefetch dp4a B group 0 and IMMA B chunk 0 of k-tile 0
    uint4 bn[4];
    uint2 ibn0, ibn1;
    {
        bn[0] = gb[(cloc0 + 0) * NG + 0];
        bn[1] = gb[(cloc0 + 1) * NG + 0];
        bn[2] = gb[(cloc0 + 8) * NG + 0];
        bn[3] = gb[(cloc0 + 9) * NG + 0];
        const int ntg0 = wn * 2;                       // kt=0, chunk 0
        ibn0 = gi[((ntg0 + 0) * 8 + 0) * 32 + lane];
        ibn1 = gi[((ntg0 + 1) * 8 + 0) * 32 + lane];
    }

    for (int kt = 0; kt < NKT; kt++) {
        int acc[4][2][4];
#pragma unroll
        for (int m = 0; m < 4; m++)
#pragma unroll
            for (int nn = 0; nn < 2; nn++)
#pragma unroll
                for (int q = 0; q < 4; q++) acc[m][nn][q] = 0;

#pragma unroll
        for (int g = 0; g < NG; g++) {
            uint4 bc[4];
#pragma unroll
            for (int q = 0; q < 4; q++) bc[q] = bn[q];

            // prefetch next dp4a B group (or group 0 of next k-tile)
            {
                int nk = (g == NG - 1) ? kt + 1 : kt;
                int ng = (g == NG - 1) ? 0 : g + 1;
                if (nk < NKT) {
                    const int cb = nk * 128 + cloc0;
                    bn[0] = gb[(cb + 0) * NG + ng];
                    bn[1] = gb[(cb + 1) * NG + ng];
                    bn[2] = gb[(cb + 8) * NG + ng];
                    bn[3] = gb[(cb + 9) * NG + ng];
                }
            }

            // IMMA burst at group head using prefetched regs, then refill.
            if (g < NC_T) {
#pragma unroll
                for (int m = 0; m < 4; m++) {
                    const int mt = wm * 4 + m;
                    uint4 av = *(const uint4*)&sA[((mt * NC_T + g) * 32 + lane) << 2];
                    imma16832(acc[m][0], av.x, av.y, av.z, av.w, ibn0.x, ibn0.y);
                    imma16832(acc[m][1], av.x, av.y, av.z, av.w, ibn1.x, ibn1.y);
                }
                int nk = (g < NC_T - 1) ? kt : kt + 1;
                int nc = (g < NC_T - 1) ? g + 1 : 0;
                if (nk < NKT) {
                    const int ntgn = nk * 16 + wn * 2;
                    ibn0 = gi[((ntgn + 0) * 8 + nc) * 32 + lane];
                    ibn1 = gi[((ntgn + 1) * 8 + nc) * 32 + lane];
                }
            }

            // dp4a: 8 rows x 4 cols x 4 dim-words
#pragma unroll
            for (int r = 0; r < 8; r++) {
                const int m = r >> 1, jr = r & 1;
                const int row = wm * 64 + m * 16 + jr * 8 + gid;
                uint4 aw = *(const uint4*)&xw[row * XW_STRIDE + g * 4];
#pragma unroll
                for (int nn = 0; nn < 2; nn++)
#pragma unroll
                    for (int j = 0; j < 2; j++) {
                        const uint4 bw = bc[nn * 2 + j];
                        int a = acc[m][nn][jr * 2 + j];
                        a = __dp4a((int)aw.x, (int)bw.x, a);
                        a = __dp4a((int)aw.y, (int)bw.y, a);
                        a = __dp4a((int)aw.z, (int)bw.z, a);
                        a = __dp4a((int)aw.w, (int)bw.w, a);
                        acc[m][nn][jr * 2 + j] = a;
                    }
            }
        }

        // ---- fold: s = e2s[col] - 2*dot (exact int32, full 256 dims) ----
#pragma unroll
        for (int nn = 0; nn < 2; nn++) {
            const int colb = kt * 128 + (wn * 2 + nn) * 8 + tig * 2;
            const int e20 = __ldg(&g_e2s[colb]);
            const int e21 = __ldg(&g_e2s[colb + 1]);
#pragma unroll
            for (int m = 0; m < 4; m++)
#pragma unroll
                for (int jr = 0; jr < 2; jr++) {
                    const int sl = m * 2 + jr;
#pragma unroll
                    for (int j = 0; j < 2; j++) {
                        int s = (j ? e21 : e20) - 2 * acc[m][nn][jr * 2 + j];
                        uint32_t p = ((uint32_t)(s + (1 << 23)) << 7) |
                                     (uint32_t)(kt * 4 + nn * 2 + j);
                        if (p < t2a[sl])      { t2b[sl] = t2a[sl]; t2a[sl] = p; }
                        else if (p < t2b[sl]) { t2b[sl] = p; }
                    }
                }
        }
    }

    // ---- emit 64 candidates per token row into smem ----
#pragma unroll
    for (int m = 0; m < 4; m++)
#pragma unroll
        for (int jr = 0; jr < 2; jr++) {
            const int sl = m * 2 + jr;
            const int rl = wm * 64 + m * 16 + jr * 8 + gid;   // local row
            const int sb = (wn * 4 + tig) * 2;
#pragma unroll
            for (int u = 0; u < 2; u++) {
                uint32_t p = u ? t2b[sl] : t2a[sl];
                int s   = (int)(p >> 7) - (1 << 23);
                int loc = (int)(p & 127);            // kt*4 + nn*2 + j
                int col = (loc >> 2) * 128 + (wn * 2 + ((loc >> 1) & 1)) * 8 +
                          tig * 2 + (loc & 1);
                scand[rl * 64 + sb + u] = make_int2(s, col);
            }
        }
    __syncthreads();

    // ---- fused rescore + gather: warp w handles local rows 8w..8w+7 ----
    for (int i = 0; i < 8; i++) {
        const int rl  = w * 8 + i;
        const int tok = n0 + rl;

        int2 c0 = scand[rl * 64 + lane];
        int2 c1 = scand[rl * 64 + lane + 32];
        long long p0 = ((long long)c0.x << 13) | (long long)c0.y;
        long long p1 = ((long long)c1.x << 13) | (long long)c1.y;
        if (p1 < p0) { long long tmp = p0; p0 = p1; p1 = tmp; }

        int sel[16];
#pragma unroll
        for (int r = 0; r < 16; r++) {
            long long mv = p0;
#pragma unroll
            for (int o = 16; o > 0; o >>= 1) {
                long long ov = __shfl_xor_sync(0xffffffffu, mv, o);
                if (ov < mv) mv = ov;
            }
            sel[r] = (int)(mv & 0x1FFF);
            if (p0 == mv) { p0 = p1; p1 = 0x7FFFFFFFFFFFFFFFLL; }
        }

        float xv[8];
#pragma unroll
        for (int q = 0; q < 8; q++) xv[q] = x[(size_t)tok * DIM + lane + 32 * q];

        float bv = 3.4e38f; int bk = KCODE;
#pragma unroll
        for (int r = 0; r < 16; r++) {
            const int k = sel[r];
            const float* e = embed + (size_t)k * DIM;
            float d = 0.f;
#pragma unroll
            for (int q = 0; q < 8; q++) d = fmaf(xv[q], e[lane + 32 * q], d);
#pragma unroll
            for (int o = 16; o > 0; o >>= 1) d += __shfl_xor_sync(0xffffffffu, d, o);
            float sc = fmaf(-2.f, d, g_e2[k]);
            if (sc < bv || (sc == bv && k < bk)) { bv = sc; bk = k; }
        }

        const float* e = embed + (size_t)bk * DIM;
#pragma unroll
        for (int q = 0; q < 8; q++)
            out[(size_t)tok * DIM + lane + 32 * q] = e[lane + 32 * q];
    }
}

// ---------------------------------------------------------------------------
extern "C" void kernel_launch(void* const* d_in, const int* in_sizes, int n_in,
                              void* d_out, int out_size) {
    const float* x     = (const float*)d_in[0];
    const float* embed = (const float*)d_in[1];
    if (n_in >= 2 && in_sizes[0] < in_sizes[1]) {
        const float* tmp = x; x = embed; embed = tmp;
    }
    float* out = (float*)d_out;

    cudaFuncSetAttribute(screen_kernel, cudaFuncAttributeMaxDynamicSharedMemorySize, SMEM_TOTAL);

    equant_kernel<<<KCODE / 8, 256>>>(embed);
    screen_kernel<<<N_TOK / BM, 512, SMEM_TOTAL>>>(x, embed, out);
}

// round 15
// speedup vs baseline: 1.0863x; 1.0863x over previous
#include <cuda_runtime.h>
#include <cstdint>

// VectorQuantize: H=1, N=32768, D=256, K=4096.
// Round 14: R12 screen verbatim (best mainloop, 455.7us) + parallelized
//           rescore: 2 warps/token, top-8 per 32-candidate half, exact fp32,
//           pair-combined winner, split gather.

#define N_TOK 32768
#define DIM   256
#define KCODE 4096
#define BM    128
#define NKT   (KCODE / 128)       // 32 k-tiles of 128 codes

#define NC_T  5                   // IMMA chunks (dims 0..159)
#define NG    6                   // dp4a groups of 16 dims (dims 160..255)
#define XW_STRIDE 28              // dp4a A row stride in words (conflict-free)
#define SA_WORDS  (8 * NC_T * 32 * 4)       // 5120
#define XW_WORDS  (BM * XW_STRIDE)          // 3584
#define SMEM_TOTAL ((SA_WORDS + XW_WORDS) * 4)

__device__ float    g_e2[KCODE];               // exact fp32 ||e||^2 (rescore)
__device__ int      g_e2s[KCODE];              // int ||q_e||^2 (screen)
__device__ uint32_t g_e8[512 * 8 * 32 * 2];    // IMMA B frags [nt][c][lane][hk]
__device__ uint32_t g_ebd[KCODE * 24];         // dp4a B [col][24 words]
__device__ int2     g_cand[N_TOK][64];

// ---------------------------------------------------------------------------
__device__ __forceinline__ void imma16832(int c[4], uint32_t a0, uint32_t a1,
                                          uint32_t a2, uint32_t a3,
                                          uint32_t b0, uint32_t b1) {
    asm volatile(
        "mma.sync.aligned.m16n8k32.row.col.s32.s8.s8.s32 "
        "{%0,%1,%2,%3}, {%4,%5,%6,%7}, {%8,%9}, {%0,%1,%2,%3};"
        : "+r"(c[0]), "+r"(c[1]), "+r"(c[2]), "+r"(c[3])
        : "r"(a0), "r"(a1), "r"(a2), "r"(a3), "r"(b0), "r"(b1));
}
__device__ __forceinline__ int q8(float v) {
    int q = __float2int_rn(v * 32.0f);
    return max(-127, min(127, q));
}
__device__ __forceinline__ uint32_t pack4(int q0, int q1, int q2, int q3) {
    return (uint32_t)(q0 & 0xFF) | ((uint32_t)(q1 & 0xFF) << 8) |
           ((uint32_t)(q2 & 0xFF) << 16) | ((uint32_t)(q3 & 0xFF) << 24);
}

// ---------------------------------------------------------------------------
// equant: embed -> IMMA fragments (dims<160) + dp4a words (dims>=160) + e2s/e2.
// ---------------------------------------------------------------------------
__global__ void equant_kernel(const float* __restrict__ embed) {
    const int n    = (blockIdx.x * blockDim.x + threadIdx.x) >> 5;
    const int lane = threadIdx.x & 31;
    if (n >= KCODE) return;
    const float* row = embed + (size_t)n * DIM;

    float4 va = *(const float4*)(row + lane * 8);
    float4 vb = *(const float4*)(row + lane * 8 + 4);
    int   qa[8] = {q8(va.x), q8(va.y), q8(va.z), q8(va.w),
                   q8(vb.x), q8(vb.y), q8(vb.z), q8(vb.w)};
    float fv[8] = {va.x, va.y, va.z, va.w, vb.x, vb.y, vb.z, vb.w};

    int s2i = 0; float s2f = 0.f;
#pragma unroll
    for (int i = 0; i < 8; i++) { s2i += qa[i] * qa[i]; s2f = fmaf(fv[i], fv[i], s2f); }
#pragma unroll
    for (int o = 16; o > 0; o >>= 1) {
        s2i += __shfl_xor_sync(0xffffffffu, s2i, o);
        s2f += __shfl_xor_sync(0xffffffffu, s2f, o);
    }
    if (lane == 0) { g_e2s[n] = s2i; g_e2[n] = s2f; }

    const int nt = n >> 3, gidn = n & 7;
#pragma unroll
    for (int u = 0; u < 2; u++) {
        uint32_t w = pack4(qa[4 * u], qa[4 * u + 1], qa[4 * u + 2], qa[4 * u + 3]);
        int k0 = lane * 8 + 4 * u;
        if (k0 < 160) {                 // IMMA fragment region (c = 0..4)
            int c = k0 >> 5, hk = (k0 >> 4) & 1, tg = (k0 >> 2) & 3;
            g_e8[(((nt * 8 + c) * 32 + gidn * 4 + tg) << 1) + hk] = w;
        } else {                        // dp4a word region
            g_ebd[n * 24 + ((k0 - 160) >> 2)] = w;
        }
    }
}

// ---------------------------------------------------------------------------
// Screen (R12 verbatim): 512 threads = 16 warps = 2 wm x 8 wn. Barrier-free
// dual-pipe mainloop, exact int32 scores, 64 candidates per token.
// ---------------------------------------------------------------------------
__global__ __launch_bounds__(512)
void screen_kernel(const float* __restrict__ x) {
    extern __shared__ uint32_t sm[];
    uint32_t* sA = sm;                    // SA_WORDS
    uint32_t* xw = sm + SA_WORDS;         // XW_WORDS (stride 28)

    const int t = threadIdx.x, lane = t & 31, w = t >> 5;
    const int wm = w & 1, wn = w >> 1;
    const int gid = lane >> 2, tig = lane & 3;
    const int n0 = blockIdx.x * BM;

#pragma unroll
    for (int i = 0; i < 16; i++) {
        int wid = t + 512 * i;
        int row = wid >> 6, wk = wid & 63, k0 = wk * 4;
        float4 v = *(const float4*)(x + (size_t)(n0 + row) * DIM + k0);
        uint32_t pw = pack4(q8(v.x), q8(v.y), q8(v.z), q8(v.w));
        if (k0 < 160) {
            int mt = row >> 4, gr = row & 7, jr = (row >> 3) & 1;
            int c = k0 >> 5, hk = (k0 >> 4) & 1, tg = (k0 >> 2) & 3;
            sA[(((mt * NC_T + c) * 32 + gr * 4 + tg) << 2) + jr + 2 * hk] = pw;
        } else {
            xw[row * XW_STRIDE + (wk - 40)] = pw;
        }
    }
    __syncthreads();

    const int cloc0 = wn * 16 + tig * 2;
    const uint4* __restrict__ gb = (const uint4*)g_ebd;
    const uint2* __restrict__ gi = (const uint2*)g_e8;

    uint32_t t2a[8], t2b[8];
#pragma unroll
    for (int s = 0; s < 8; s++) { t2a[s] = 0xFFFFFFFFu; t2b[s] = 0xFFFFFFFFu; }

    uint4 bn[4];
    uint2 ibn0, ibn1;
    {
        bn[0] = gb[(cloc0 + 0) * NG + 0];
        bn[1] = gb[(cloc0 + 1) * NG + 0];
        bn[2] = gb[(cloc0 + 8) * NG + 0];
        bn[3] = gb[(cloc0 + 9) * NG + 0];
        const int ntg0 = wn * 2;
        ibn0 = gi[((ntg0 + 0) * 8 + 0) * 32 + lane];
        ibn1 = gi[((ntg0 + 1) * 8 + 0) * 32 + lane];
    }

    for (int kt = 0; kt < NKT; kt++) {
        int acc[4][2][4];
#pragma unroll
        for (int m = 0; m < 4; m++)
#pragma unroll
            for (int nn = 0; nn < 2; nn++)
#pragma unroll
                for (int q = 0; q < 4; q++) acc[m][nn][q] = 0;

#pragma unroll
        for (int g = 0; g < NG; g++) {
            uint4 bc[4];
#pragma unroll
            for (int q = 0; q < 4; q++) bc[q] = bn[q];

            {
                int nk = (g == NG - 1) ? kt + 1 : kt;
                int ng = (g == NG - 1) ? 0 : g + 1;
                if (nk < NKT) {
                    const int cb = nk * 128 + cloc0;
                    bn[0] = gb[(cb + 0) * NG + ng];
                    bn[1] = gb[(cb + 1) * NG + ng];
                    bn[2] = gb[(cb + 8) * NG + ng];
                    bn[3] = gb[(cb + 9) * NG + ng];
                }
            }

            if (g < NC_T) {
#pragma unroll
                for (int m = 0; m < 4; m++) {
                    const int mt = wm * 4 + m;
                    uint4 av = *(const uint4*)&sA[((mt * NC_T + g) * 32 + lane) << 2];
                    imma16832(acc[m][0], av.x, av.y, av.z, av.w, ibn0.x, ibn0.y);
                    imma16832(acc[m][1], av.x, av.y, av.z, av.w, ibn1.x, ibn1.y);
                }
                int nk = (g < NC_T - 1) ? kt : kt + 1;
                int nc = (g < NC_T - 1) ? g + 1 : 0;
                if (nk < NKT) {
                    const int ntgn = nk * 16 + wn * 2;
                    ibn0 = gi[((ntgn + 0) * 8 + nc) * 32 + lane];
                    ibn1 = gi[((ntgn + 1) * 8 + nc) * 32 + lane];
                }
            }

#pragma unroll
            for (int r = 0; r < 8; r++) {
                const int m = r >> 1, jr = r & 1;
                const int row = wm * 64 + m * 16 + jr * 8 + gid;
                uint4 aw = *(const uint4*)&xw[row * XW_STRIDE + g * 4];
#pragma unroll
                for (int nn = 0; nn < 2; nn++)
#pragma unroll
                    for (int j = 0; j < 2; j++) {
                        const uint4 bw = bc[nn * 2 + j];
                        int a = acc[m][nn][jr * 2 + j];
                        a = __dp4a((int)aw.x, (int)bw.x, a);
                        a = __dp4a((int)aw.y, (int)bw.y, a);
                        a = __dp4a((int)aw.z, (int)bw.z, a);
                        a = __dp4a((int)aw.w, (int)bw.w, a);
                        acc[m][nn][jr * 2 + j] = a;
                    }
            }
        }

#pragma unroll
        for (int nn = 0; nn < 2; nn++) {
            const int colb = kt * 128 + (wn * 2 + nn) * 8 + tig * 2;
            const int e20 = __ldg(&g_e2s[colb]);
            const int e21 = __ldg(&g_e2s[colb + 1]);
#pragma unroll
            for (int m = 0; m < 4; m++)
#pragma unroll
                for (int jr = 0; jr < 2; jr++) {
                    const int sl = m * 2 + jr;
#pragma unroll
                    for (int j = 0; j < 2; j++) {
                        int s = (j ? e21 : e20) - 2 * acc[m][nn][jr * 2 + j];
                        uint32_t p = ((uint32_t)(s + (1 << 23)) << 7) |
                                     (uint32_t)(kt * 4 + nn * 2 + j);
                        if (p < t2a[sl])      { t2b[sl] = t2a[sl]; t2a[sl] = p; }
                        else if (p < t2b[sl]) { t2b[sl] = p; }
                    }
                }
        }
    }

#pragma unroll
    for (int m = 0; m < 4; m++)
#pragma unroll
        for (int jr = 0; jr < 2; jr++) {
            const int sl  = m * 2 + jr;
            const int row = n0 + wm * 64 + m * 16 + jr * 8 + gid;
            const int sb  = (wn * 4 + tig) * 2;
#pragma unroll
            for (int u = 0; u < 2; u++) {
                uint32_t p = u ? t2b[sl] : t2a[sl];
                int s   = (int)(p >> 7) - (1 << 23);
                int loc = (int)(p & 127);
                int col = (loc >> 2) * 128 + (wn * 2 + ((loc >> 1) & 1)) * 8 +
                          tig * 2 + (loc & 1);
                g_cand[row][sb + u] = make_int2(s, col);
            }
        }
}

// ---------------------------------------------------------------------------
// Rescore: 2 warps per token (halves of 32 candidates each). Each warp:
// top-8 of its half by screen score (true best = min of its half, always
// kept), exact fp32 rescoring, pair-combine via smem (score, smaller index),
// each warp gathers half the winning row.
// ---------------------------------------------------------------------------
__global__ __launch_bounds__(256)
void rescore_kernel(const float* __restrict__ x, const float* __restrict__ embed,
                    float* __restrict__ out) {
    __shared__ float sbv[8];
    __shared__ int   sbk[8];
    const int wp   = threadIdx.x >> 5;              // 0..7
    const int lane = threadIdx.x & 31;
    const int tok  = blockIdx.x * 4 + (wp >> 1);
    const int half = wp & 1;

    int2 c = g_cand[tok][half * 32 + lane];
    long long p = ((long long)c.x << 13) | (long long)c.y;

    int sel[8];
#pragma unroll
    for (int r = 0; r < 8; r++) {
        long long mv = p;
#pragma unroll
        for (int o = 16; o > 0; o >>= 1) {
            long long ov = __shfl_xor_sync(0xffffffffu, mv, o);
            if (ov < mv) mv = ov;
        }
        sel[r] = (int)(mv & 0x1FFF);
        if (p == mv) p = 0x7FFFFFFFFFFFFFFFLL;
    }

    float xv[8];
#pragma unroll
    for (int q = 0; q < 8; q++) xv[q] = x[(size_t)tok * DIM + lane + 32 * q];

    float bv = 3.4e38f; int bk = KCODE;
#pragma unroll
    for (int r = 0; r < 8; r++) {
        const int k = sel[r];
        const float* e = embed + (size_t)k * DIM;
        float d = 0.f;
#pragma unroll
        for (int q = 0; q < 8; q++) d = fmaf(xv[q], e[lane + 32 * q], d);
#pragma unroll
        for (int o = 16; o > 0; o >>= 1) d += __shfl_xor_sync(0xffffffffu, d, o);
        float sc = fmaf(-2.f, d, g_e2[k]);
        if (sc < bv || (sc == bv && k < bk)) { bv = sc; bk = k; }
    }

    if (lane == 0) { sbv[wp] = bv; sbk[wp] = bk; }
    __syncthreads();

    const int base = wp & ~1;
    float v0 = sbv[base],     v1 = sbv[base + 1];
    int   k0 = sbk[base],     k1 = sbk[base + 1];
    const int bkf = (v1 < v0 || (v1 == v0 && k1 < k0)) ? k1 : k0;

    // each warp gathers its half of the winning codeword (128 dims)
    const float* e = embed + (size_t)bkf * DIM + half * 128;
    float4 val = *(const float4*)(e + lane * 4);
    *(float4*)(out + (size_t)tok * DIM + half * 128 + lane * 4) = val;
}

// ---------------------------------------------------------------------------
extern "C" void kernel_launch(void* const* d_in, const int* in_sizes, int n_in,
                              void* d_out, int out_size) {
    const float* x     = (const float*)d_in[0];
    const float* embed = (const float*)d_in[1];
    if (n_in >= 2 && in_sizes[0] < in_sizes[1]) {
        const float* tmp = x; x = embed; embed = tmp;
    }
    float* out = (float*)d_out;

    cudaFuncSetAttribute(screen_kernel, cudaFuncAttributeMaxDynamicSharedMemorySize, SMEM_TOTAL);

    equant_kernel<<<KCODE / 8, 256>>>(embed);
    screen_kernel<<<N_TOK / BM, 512, SMEM_TOTAL>>>(x);
    rescore_kernel<<<N_TOK / 4, 256>>>(x, embed, out);
}

// round 16
// speedup vs baseline: 1.1336x; 1.0435x over previous
#include <cuda_runtime.h>
#include <cstdint>

// VectorQuantize: H=1, N=32768, D=256, K=4096.
// Round 16: R12 dual-pipe screen, K-split x4 (each CTA: 128 tokens x 1024
//           codes; grid 1024) to fix wave quantization (2.0 -> 1.75 waves).
//           Per-CTA tig-merged top-2 per (row,wn) over 128-code streams.
//           Exact int32 scores; 64 candidates; exact fp32 top-16 rescore.

#define N_TOK 32768
#define DIM   256
#define KCODE 4096
#define BM    128
#define NKT   (KCODE / 128)       // 32 k-tiles of 128 codes (global)
#define KSPL  4                   // K-split factor
#define NKTC  (NKT / KSPL)        // 8 k-tiles per CTA

#define NC_T  5                   // IMMA chunks (dims 0..159)
#define NG    6                   // dp4a groups of 16 dims (dims 160..255)
#define XW_STRIDE 28              // dp4a A row stride in words (conflict-free)
#define SA_WORDS  (8 * NC_T * 32 * 4)       // 5120
#define XW_WORDS  (BM * XW_STRIDE)          // 3584
#define SMEM_TOTAL ((SA_WORDS + XW_WORDS) * 4)

__device__ float    g_e2[KCODE];               // exact fp32 ||e||^2 (rescore)
__device__ int      g_e2s[KCODE];              // int ||q_e||^2 (screen)
__device__ uint32_t g_e8[512 * 8 * 32 * 2];    // IMMA B frags [nt][c][lane][hk]
__device__ uint32_t g_ebd[KCODE * 24];         // dp4a B [col][24 words]
__device__ int2     g_cand[N_TOK][64];

// ---------------------------------------------------------------------------
__device__ __forceinline__ void imma16832(int c[4], uint32_t a0, uint32_t a1,
                                          uint32_t a2, uint32_t a3,
                                          uint32_t b0, uint32_t b1) {
    asm volatile(
        "mma.sync.aligned.m16n8k32.row.col.s32.s8.s8.s32 "
        "{%0,%1,%2,%3}, {%4,%5,%6,%7}, {%8,%9}, {%0,%1,%2,%3};"
        : "+r"(c[0]), "+r"(c[1]), "+r"(c[2]), "+r"(c[3])
        : "r"(a0), "r"(a1), "r"(a2), "r"(a3), "r"(b0), "r"(b1));
}
__device__ __forceinline__ int q8(float v) {
    int q = __float2int_rn(v * 32.0f);
    return max(-127, min(127, q));
}
__device__ __forceinline__ uint32_t pack4(int q0, int q1, int q2, int q3) {
    return (uint32_t)(q0 & 0xFF) | ((uint32_t)(q1 & 0xFF) << 8) |
           ((uint32_t)(q2 & 0xFF) << 16) | ((uint32_t)(q3 & 0xFF) << 24);
}

// ---------------------------------------------------------------------------
// equant: embed -> IMMA fragments (dims<160) + dp4a words (dims>=160) + e2s/e2.
// ---------------------------------------------------------------------------
__global__ void equant_kernel(const float* __restrict__ embed) {
    const int n    = (blockIdx.x * blockDim.x + threadIdx.x) >> 5;
    const int lane = threadIdx.x & 31;
    if (n >= KCODE) return;
    const float* row = embed + (size_t)n * DIM;

    float4 va = *(const float4*)(row + lane * 8);
    float4 vb = *(const float4*)(row + lane * 8 + 4);
    int   qa[8] = {q8(va.x), q8(va.y), q8(va.z), q8(va.w),
                   q8(vb.x), q8(vb.y), q8(vb.z), q8(vb.w)};
    float fv[8] = {va.x, va.y, va.z, va.w, vb.x, vb.y, vb.z, vb.w};

    int s2i = 0; float s2f = 0.f;
#pragma unroll
    for (int i = 0; i < 8; i++) { s2i += qa[i] * qa[i]; s2f = fmaf(fv[i], fv[i], s2f); }
#pragma unroll
    for (int o = 16; o > 0; o >>= 1) {
        s2i += __shfl_xor_sync(0xffffffffu, s2i, o);
        s2f += __shfl_xor_sync(0xffffffffu, s2f, o);
    }
    if (lane == 0) { g_e2s[n] = s2i; g_e2[n] = s2f; }

    const int nt = n >> 3, gidn = n & 7;
#pragma unroll
    for (int u = 0; u < 2; u++) {
        uint32_t w = pack4(qa[4 * u], qa[4 * u + 1], qa[4 * u + 2], qa[4 * u + 3]);
        int k0 = lane * 8 + 4 * u;
        if (k0 < 160) {                 // IMMA fragment region (c = 0..4)
            int c = k0 >> 5, hk = (k0 >> 4) & 1, tg = (k0 >> 2) & 3;
            g_e8[(((nt * 8 + c) * 32 + gidn * 4 + tg) << 1) + hk] = w;
        } else {                        // dp4a word region
            g_ebd[n * 24 + ((k0 - 160) >> 2)] = w;
        }
    }
}

// ---------------------------------------------------------------------------
// Screen: blockIdx = tile*4 + kq. 512 threads = 16 warps = 2 wm x 8 wn.
// Each CTA: 128 tokens vs codes [kq*1024, kq*1024+1024). Mainloop = R12.
// Epilogue: merge top-2 across tig (shuffle), emit 2 cand per (row,wn).
// ---------------------------------------------------------------------------
__global__ __launch_bounds__(512)
void screen_kernel(const float* __restrict__ x) {
    extern __shared__ uint32_t sm[];
    uint32_t* sA = sm;                    // SA_WORDS
    uint32_t* xw = sm + SA_WORDS;         // XW_WORDS (stride 28)

    const int t = threadIdx.x, lane = t & 31, w = t >> 5;
    const int wm = w & 1, wn = w >> 1;
    const int gid = lane >> 2, tig = lane & 3;
    const int kq   = blockIdx.x & (KSPL - 1);
    const int n0   = (blockIdx.x >> 2) * BM;
    const int kbeg = kq * NKTC, kend = kbeg + NKTC;

    // ---- stage A: IMMA fragments (dims<160) + dp4a words (dims>=160) ----
#pragma unroll
    for (int i = 0; i < 16; i++) {
        int wid = t + 512 * i;
        int row = wid >> 6, wk = wid & 63, k0 = wk * 4;
        float4 v = *(const float4*)(x + (size_t)(n0 + row) * DIM + k0);
        uint32_t pw = pack4(q8(v.x), q8(v.y), q8(v.z), q8(v.w));
        if (k0 < 160) {
            int mt = row >> 4, gr = row & 7, jr = (row >> 3) & 1;
            int c = k0 >> 5, hk = (k0 >> 4) & 1, tg = (k0 >> 2) & 3;
            sA[(((mt * NC_T + c) * 32 + gr * 4 + tg) << 2) + jr + 2 * hk] = pw;
        } else {
            xw[row * XW_STRIDE + (wk - 40)] = pw;
        }
    }
    __syncthreads();

    const int cloc0 = wn * 16 + tig * 2;
    const uint4* __restrict__ gb = (const uint4*)g_ebd;
    const uint2* __restrict__ gi = (const uint2*)g_e8;

    uint32_t t2a[8], t2b[8];
#pragma unroll
    for (int s = 0; s < 8; s++) { t2a[s] = 0xFFFFFFFFu; t2b[s] = 0xFFFFFFFFu; }

    // prologue: prefetch dp4a B group 0 and IMMA B chunk 0 of k-tile kbeg
    uint4 bn[4];
    uint2 ibn0, ibn1;
    {
        const int cb = kbeg * 128 + cloc0;
        bn[0] = gb[(cb + 0) * NG + 0];
        bn[1] = gb[(cb + 1) * NG + 0];
        bn[2] = gb[(cb + 8) * NG + 0];
        bn[3] = gb[(cb + 9) * NG + 0];
        const int ntg0 = kbeg * 16 + wn * 2;
        ibn0 = gi[((ntg0 + 0) * 8 + 0) * 32 + lane];
        ibn1 = gi[((ntg0 + 1) * 8 + 0) * 32 + lane];
    }

    for (int kt = kbeg; kt < kend; kt++) {
        int acc[4][2][4];
#pragma unroll
        for (int m = 0; m < 4; m++)
#pragma unroll
            for (int nn = 0; nn < 2; nn++)
#pragma unroll
                for (int q = 0; q < 4; q++) acc[m][nn][q] = 0;

#pragma unroll
        for (int g = 0; g < NG; g++) {
            uint4 bc[4];
#pragma unroll
            for (int q = 0; q < 4; q++) bc[q] = bn[q];

            {
                int nk = (g == NG - 1) ? kt + 1 : kt;
                int ng = (g == NG - 1) ? 0 : g + 1;
                if (nk < kend) {
                    const int cb = nk * 128 + cloc0;
                    bn[0] = gb[(cb + 0) * NG + ng];
                    bn[1] = gb[(cb + 1) * NG + ng];
                    bn[2] = gb[(cb + 8) * NG + ng];
                    bn[3] = gb[(cb + 9) * NG + ng];
                }
            }

            if (g < NC_T) {
#pragma unroll
                for (int m = 0; m < 4; m++) {
                    const int mt = wm * 4 + m;
                    uint4 av = *(const uint4*)&sA[((mt * NC_T + g) * 32 + lane) << 2];
                    imma16832(acc[m][0], av.x, av.y, av.z, av.w, ibn0.x, ibn0.y);
                    imma16832(acc[m][1], av.x, av.y, av.z, av.w, ibn1.x, ibn1.y);
                }
                int nk = (g < NC_T - 1) ? kt : kt + 1;
                int nc = (g < NC_T - 1) ? g + 1 : 0;
                if (nk < kend) {
                    const int ntgn = nk * 16 + wn * 2;
                    ibn0 = gi[((ntgn + 0) * 8 + nc) * 32 + lane];
                    ibn1 = gi[((ntgn + 1) * 8 + nc) * 32 + lane];
                }
            }

#pragma unroll
            for (int r = 0; r < 8; r++) {
                const int m = r >> 1, jr = r & 1;
                const int row = wm * 64 + m * 16 + jr * 8 + gid;
                uint4 aw = *(const uint4*)&xw[row * XW_STRIDE + g * 4];
#pragma unroll
                for (int nn = 0; nn < 2; nn++)
#pragma unroll
                    for (int j = 0; j < 2; j++) {
                        const uint4 bw = bc[nn * 2 + j];
                        int a = acc[m][nn][jr * 2 + j];
                        a = __dp4a((int)aw.x, (int)bw.x, a);
                        a = __dp4a((int)aw.y, (int)bw.y, a);
                        a = __dp4a((int)aw.z, (int)bw.z, a);
                        a = __dp4a((int)aw.w, (int)bw.w, a);
                        acc[m][nn][jr * 2 + j] = a;
                    }
            }
        }

        // ---- fold: s = e2s[col] - 2*dot; loc = (ktl,nn,tig,j) col-monotonic
        const int ktl = kt - kbeg;
#pragma unroll
        for (int nn = 0; nn < 2; nn++) {
            const int colb = kt * 128 + (wn * 2 + nn) * 8 + tig * 2;
            const int e20 = __ldg(&g_e2s[colb]);
            const int e21 = __ldg(&g_e2s[colb + 1]);
#pragma unroll
            for (int m = 0; m < 4; m++)
#pragma unroll
                for (int jr = 0; jr < 2; jr++) {
                    const int sl = m * 2 + jr;
#pragma unroll
                    for (int j = 0; j < 2; j++) {
                        int s = (j ? e21 : e20) - 2 * acc[m][nn][jr * 2 + j];
                        uint32_t p = ((uint32_t)(s + (1 << 23)) << 7) |
                                     (uint32_t)(ktl * 16 + nn * 8 + tig * 2 + j);
                        if (p < t2a[sl])      { t2b[sl] = t2a[sl]; t2a[sl] = p; }
                        else if (p < t2b[sl]) { t2b[sl] = p; }
                    }
                }
        }
    }

    // ---- merge top-2 across tig lanes (shuffle), emit 2 cand per (row,wn)
#pragma unroll
    for (int m = 0; m < 4; m++)
#pragma unroll
        for (int jr = 0; jr < 2; jr++) {
            const int sl = m * 2 + jr;
            uint32_t a = t2a[sl], b = t2b[sl];
#pragma unroll
            for (int o = 1; o <= 2; o <<= 1) {
                uint32_t oa = __shfl_xor_sync(0xffffffffu, a, o);
                uint32_t ob = __shfl_xor_sync(0xffffffffu, b, o);
                uint32_t na = min(a, oa);
                uint32_t nb = min(max(a, oa), min(b, ob));
                a = na; b = nb;
            }
            if (tig == 0) {
                const int row  = n0 + wm * 64 + m * 16 + jr * 8 + gid;
                const int base = kq * 16 + wn * 2;
#pragma unroll
                for (int u = 0; u < 2; u++) {
                    uint32_t p = u ? b : a;
                    int s    = (int)(p >> 7) - (1 << 23);
                    int loc  = (int)(p & 127);
                    int ktl2 = loc >> 4, nn2 = (loc >> 3) & 1;
                    int tg2  = (loc >> 1) & 3, j2 = loc & 1;
                    int col  = (kbeg + ktl2) * 128 + (wn * 2 + nn2) * 8 +
                               tg2 * 2 + j2;
                    g_cand[row][base + u] = make_int2(s, col);
                }
            }
        }
}

// ---------------------------------------------------------------------------
// Rescore: warp per token. Top-16 of 64 candidates, exact fp32, gather winner.
// ---------------------------------------------------------------------------
__global__ __launch_bounds__(256)
void rescore_kernel(const float* __restrict__ x, const float* __restrict__ embed,
                    float* __restrict__ out) {
    const int tok  = (blockIdx.x * blockDim.x + threadIdx.x) >> 5;
    const int lane = threadIdx.x & 31;
    if (tok >= N_TOK) return;

    int2 c0 = g_cand[tok][lane];
    int2 c1 = g_cand[tok][lane + 32];
    long long p0 = ((long long)c0.x << 13) | (long long)c0.y;
    long long p1 = ((long long)c1.x << 13) | (long long)c1.y;
    if (p1 < p0) { long long tmp = p0; p0 = p1; p1 = tmp; }

    int sel[16];
#pragma unroll
    for (int r = 0; r < 16; r++) {
        long long mv = p0;
#pragma unroll
        for (int o = 16; o > 0; o >>= 1) {
            long long ov = __shfl_xor_sync(0xffffffffu, mv, o);
            if (ov < mv) mv = ov;
        }
        sel[r] = (int)(mv & 0x1FFF);
        if (p0 == mv) { p0 = p1; p1 = 0x7FFFFFFFFFFFFFFFLL; }
    }

    float xv[8];
#pragma unroll
    for (int q = 0; q < 8; q++) xv[q] = x[(size_t)tok * DIM + lane + 32 * q];

    float bv = 3.4e38f; int bk = KCODE;
#pragma unroll
    for (int r = 0; r < 16; r++) {
        const int k = sel[r];
        const float* e = embed + (size_t)k * DIM;
        float d = 0.f;
#pragma unroll
        for (int q = 0; q < 8; q++) d = fmaf(xv[q], e[lane + 32 * q], d);
#pragma unroll
        for (int o = 16; o > 0; o >>= 1) d += __shfl_xor_sync(0xffffffffu, d, o);
        float sc = fmaf(-2.f, d, g_e2[k]);
        if (sc < bv || (sc == bv && k < bk)) { bv = sc; bk = k; }
    }

    const float* e = embed + (size_t)bk * DIM;
#pragma unroll
    for (int q = 0; q < 8; q++)
        out[(size_t)tok * DIM + lane + 32 * q] = e[lane + 32 * q];
}

// ---------------------------------------------------------------------------
extern "C" void kernel_launch(void* const* d_in, const int* in_sizes, int n_in,
                              void* d_out, int out_size) {
    const float* x     = (const float*)d_in[0];
    const float* embed = (const float*)d_in[1];
    if (n_in >= 2 && in_sizes[0] < in_sizes[1]) {
        const float* tmp = x; x = embed; embed = tmp;
    }
    float* out = (float*)d_out;

    cudaFuncSetAttribute(screen_kernel, cudaFuncAttributeMaxDynamicSharedMemorySize, SMEM_TOTAL);

    equant_kernel<<<KCODE / 8, 256>>>(embed);
    screen_kernel<<<(N_TOK / BM) * KSPL, 512, SMEM_TOTAL>>>(x);
    rescore_kernel<<<N_TOK / 8, 256>>>(x, embed, out);
}

// round 17
// speedup vs baseline: 1.1490x; 1.0136x over previous
#include <cuda_runtime.h>
#include <cstdint>

// VectorQuantize: H=1, N=32768, D=256, K=4096.
// Round 17: R16 K-split screen re-tiled to BM=64 / 256 threads / 8 warps with
//           __launch_bounds__(256,2) -> 2 CTAs/SM (same 16 warps/SM), hiding
//           per-CTA staging/epilogue under the co-resident CTA's mainloop and
//           smoothing the tail wave. Mainloop per warp identical to R16.
//           Exact int32 scores; 64 candidates; exact fp32 top-16 rescore.

#define N_TOK 32768
#define DIM   256
#define KCODE 4096
#define BM    64
#define NKT   (KCODE / 128)       // 32 k-tiles of 128 codes (global)
#define KSPL  4                   // K-split factor
#define NKTC  (NKT / KSPL)        // 8 k-tiles per CTA

#define NC_T  5                   // IMMA chunks (dims 0..159)
#define NG    6                   // dp4a groups of 16 dims (dims 160..255)
#define XW_STRIDE 28              // dp4a A row stride in words (conflict-free)
#define NMT   (BM / 16)           // 4 m-tiles
#define SA_WORDS  (NMT * NC_T * 32 * 4)     // 2560
#define XW_WORDS  (BM * XW_STRIDE)          // 1792
#define SMEM_TOTAL ((SA_WORDS + XW_WORDS) * 4)

__device__ float    g_e2[KCODE];               // exact fp32 ||e||^2 (rescore)
__device__ int      g_e2s[KCODE];              // int ||q_e||^2 (screen)
__device__ uint32_t g_e8[512 * 8 * 32 * 2];    // IMMA B frags [nt][c][lane][hk]
__device__ uint32_t g_ebd[KCODE * 24];         // dp4a B [col][24 words]
__device__ int2     g_cand[N_TOK][64];

// ---------------------------------------------------------------------------
__device__ __forceinline__ void imma16832(int c[4], uint32_t a0, uint32_t a1,
                                          uint32_t a2, uint32_t a3,
                                          uint32_t b0, uint32_t b1) {
    asm volatile(
        "mma.sync.aligned.m16n8k32.row.col.s32.s8.s8.s32 "
        "{%0,%1,%2,%3}, {%4,%5,%6,%7}, {%8,%9}, {%0,%1,%2,%3};"
        : "+r"(c[0]), "+r"(c[1]), "+r"(c[2]), "+r"(c[3])
        : "r"(a0), "r"(a1), "r"(a2), "r"(a3), "r"(b0), "r"(b1));
}
__device__ __forceinline__ int q8(float v) {
    int q = __float2int_rn(v * 32.0f);
    return max(-127, min(127, q));
}
__device__ __forceinline__ uint32_t pack4(int q0, int q1, int q2, int q3) {
    return (uint32_t)(q0 & 0xFF) | ((uint32_t)(q1 & 0xFF) << 8) |
           ((uint32_t)(q2 & 0xFF) << 16) | ((uint32_t)(q3 & 0xFF) << 24);
}

// ---------------------------------------------------------------------------
// equant: embed -> IMMA fragments (dims<160) + dp4a words (dims>=160) + e2s/e2.
// ---------------------------------------------------------------------------
__global__ void equant_kernel(const float* __restrict__ embed) {
    const int n    = (blockIdx.x * blockDim.x + threadIdx.x) >> 5;
    const int lane = threadIdx.x & 31;
    if (n >= KCODE) return;
    const float* row = embed + (size_t)n * DIM;

    float4 va = *(const float4*)(row + lane * 8);
    float4 vb = *(const float4*)(row + lane * 8 + 4);
    int   qa[8] = {q8(va.x), q8(va.y), q8(va.z), q8(va.w),
                   q8(vb.x), q8(vb.y), q8(vb.z), q8(vb.w)};
    float fv[8] = {va.x, va.y, va.z, va.w, vb.x, vb.y, vb.z, vb.w};

    int s2i = 0; float s2f = 0.f;
#pragma unroll
    for (int i = 0; i < 8; i++) { s2i += qa[i] * qa[i]; s2f = fmaf(fv[i], fv[i], s2f); }
#pragma unroll
    for (int o = 16; o > 0; o >>= 1) {
        s2i += __shfl_xor_sync(0xffffffffu, s2i, o);
        s2f += __shfl_xor_sync(0xffffffffu, s2f, o);
    }
    if (lane == 0) { g_e2s[n] = s2i; g_e2[n] = s2f; }

    const int nt = n >> 3, gidn = n & 7;
#pragma unroll
    for (int u = 0; u < 2; u++) {
        uint32_t w = pack4(qa[4 * u], qa[4 * u + 1], qa[4 * u + 2], qa[4 * u + 3]);
        int k0 = lane * 8 + 4 * u;
        if (k0 < 160) {                 // IMMA fragment region (c = 0..4)
            int c = k0 >> 5, hk = (k0 >> 4) & 1, tg = (k0 >> 2) & 3;
            g_e8[(((nt * 8 + c) * 32 + gidn * 4 + tg) << 1) + hk] = w;
        } else {                        // dp4a word region
            g_ebd[n * 24 + ((k0 - 160) >> 2)] = w;
        }
    }
}

// ---------------------------------------------------------------------------
// Screen: blockIdx = tile*KSPL + kq. 256 threads = 8 warps (wn = warp id).
// Each CTA: 64 tokens vs codes [kq*1024, (kq+1)*1024). Per-warp mainloop
// identical to R16 (wm == 0). 2 CTAs/SM via launch bounds.
// ---------------------------------------------------------------------------
__global__ __launch_bounds__(256, 2)
void screen_kernel(const float* __restrict__ x) {
    extern __shared__ uint32_t sm[];
    uint32_t* sA = sm;                    // SA_WORDS
    uint32_t* xw = sm + SA_WORDS;         // XW_WORDS (stride 28)

    const int t = threadIdx.x, lane = t & 31, wn = t >> 5;
    const int gid = lane >> 2, tig = lane & 3;
    const int kq   = blockIdx.x & (KSPL - 1);
    const int n0   = (blockIdx.x >> 2) * BM;
    const int kbeg = kq * NKTC, kend = kbeg + NKTC;

    // ---- stage A: IMMA fragments (dims<160) + dp4a words (dims>=160) ----
#pragma unroll
    for (int i = 0; i < 16; i++) {
        int wid = t + 256 * i;            // 4096 words = 64 rows x 64 words
        int row = wid >> 6, wk = wid & 63, k0 = wk * 4;
        float4 v = *(const float4*)(x + (size_t)(n0 + row) * DIM + k0);
        uint32_t pw = pack4(q8(v.x), q8(v.y), q8(v.z), q8(v.w));
        if (k0 < 160) {
            int mt = row >> 4, gr = row & 7, jr = (row >> 3) & 1;
            int c = k0 >> 5, hk = (k0 >> 4) & 1, tg = (k0 >> 2) & 3;
            sA[(((mt * NC_T + c) * 32 + gr * 4 + tg) << 2) + jr + 2 * hk] = pw;
        } else {
            xw[row * XW_STRIDE + (wk - 40)] = pw;
        }
    }
    __syncthreads();

    const int cloc0 = wn * 16 + tig * 2;
    const uint4* __restrict__ gb = (const uint4*)g_ebd;
    const uint2* __restrict__ gi = (const uint2*)g_e8;

    uint32_t t2a[8], t2b[8];
#pragma unroll
    for (int s = 0; s < 8; s++) { t2a[s] = 0xFFFFFFFFu; t2b[s] = 0xFFFFFFFFu; }

    // prologue: prefetch dp4a B group 0 and IMMA B chunk 0 of k-tile kbeg
    uint4 bn[4];
    uint2 ibn0, ibn1;
    {
        const int cb = kbeg * 128 + cloc0;
        bn[0] = gb[(cb + 0) * NG + 0];
        bn[1] = gb[(cb + 1) * NG + 0];
        bn[2] = gb[(cb + 8) * NG + 0];
        bn[3] = gb[(cb + 9) * NG + 0];
        const int ntg0 = kbeg * 16 + wn * 2;
        ibn0 = gi[((ntg0 + 0) * 8 + 0) * 32 + lane];
        ibn1 = gi[((ntg0 + 1) * 8 + 0) * 32 + lane];
    }

    for (int kt = kbeg; kt < kend; kt++) {
        int acc[4][2][4];
#pragma unroll
        for (int m = 0; m < 4; m++)
#pragma unroll
            for (int nn = 0; nn < 2; nn++)
#pragma unroll
                for (int q = 0; q < 4; q++) acc[m][nn][q] = 0;

#pragma unroll
        for (int g = 0; g < NG; g++) {
            uint4 bc[4];
#pragma unroll
            for (int q = 0; q < 4; q++) bc[q] = bn[q];

            {
                int nk = (g == NG - 1) ? kt + 1 : kt;
                int ng = (g == NG - 1) ? 0 : g + 1;
                if (nk < kend) {
                    const int cb = nk * 128 + cloc0;
                    bn[0] = gb[(cb + 0) * NG + ng];
                    bn[1] = gb[(cb + 1) * NG + ng];
                    bn[2] = gb[(cb + 8) * NG + ng];
                    bn[3] = gb[(cb + 9) * NG + ng];
                }
            }

            if (g < NC_T) {
#pragma unroll
                for (int m = 0; m < 4; m++) {
                    uint4 av = *(const uint4*)&sA[((m * NC_T + g) * 32 + lane) << 2];
                    imma16832(acc[m][0], av.x, av.y, av.z, av.w, ibn0.x, ibn0.y);
                    imma16832(acc[m][1], av.x, av.y, av.z, av.w, ibn1.x, ibn1.y);
                }
                int nk = (g < NC_T - 1) ? kt : kt + 1;
                int nc = (g < NC_T - 1) ? g + 1 : 0;
                if (nk < kend) {
                    const int ntgn = nk * 16 + wn * 2;
                    ibn0 = gi[((ntgn + 0) * 8 + nc) * 32 + lane];
                    ibn1 = gi[((ntgn + 1) * 8 + nc) * 32 + lane];
                }
            }

#pragma unroll
            for (int r = 0; r < 8; r++) {
                const int m = r >> 1, jr = r & 1;
                const int row = m * 16 + jr * 8 + gid;
                uint4 aw = *(const uint4*)&xw[row * XW_STRIDE + g * 4];
#pragma unroll
                for (int nn = 0; nn < 2; nn++)
#pragma unroll
                    for (int j = 0; j < 2; j++) {
                        const uint4 bw = bc[nn * 2 + j];
                        int a = acc[m][nn][jr * 2 + j];
                        a = __dp4a((int)aw.x, (int)bw.x, a);
                        a = __dp4a((int)aw.y, (int)bw.y, a);
                        a = __dp4a((int)aw.z, (int)bw.z, a);
                        a = __dp4a((int)aw.w, (int)bw.w, a);
                        acc[m][nn][jr * 2 + j] = a;
                    }
            }
        }

        // ---- fold: s = e2s[col] - 2*dot; loc = (ktl,nn,tig,j) col-monotonic
        const int ktl = kt - kbeg;
#pragma unroll
        for (int nn = 0; nn < 2; nn++) {
            const int colb = kt * 128 + (wn * 2 + nn) * 8 + tig * 2;
            const int e20 = __ldg(&g_e2s[colb]);
            const int e21 = __ldg(&g_e2s[colb + 1]);
#pragma unroll
            for (int m = 0; m < 4; m++)
#pragma unroll
                for (int jr = 0; jr < 2; jr++) {
                    const int sl = m * 2 + jr;
#pragma unroll
                    for (int j = 0; j < 2; j++) {
                        int s = (j ? e21 : e20) - 2 * acc[m][nn][jr * 2 + j];
                        uint32_t p = ((uint32_t)(s + (1 << 23)) << 7) |
                                     (uint32_t)(ktl * 16 + nn * 8 + tig * 2 + j);
                        if (p < t2a[sl])      { t2b[sl] = t2a[sl]; t2a[sl] = p; }
                        else if (p < t2b[sl]) { t2b[sl] = p; }
                    }
                }
        }
    }

    // ---- merge top-2 across tig lanes (shuffle), emit 2 cand per (row,wn)
#pragma unroll
    for (int m = 0; m < 4; m++)
#pragma unroll
        for (int jr = 0; jr < 2; jr++) {
            const int sl = m * 2 + jr;
            uint32_t a = t2a[sl], b = t2b[sl];
#pragma unroll
            for (int o = 1; o <= 2; o <<= 1) {
                uint32_t oa = __shfl_xor_sync(0xffffffffu, a, o);
                uint32_t ob = __shfl_xor_sync(0xffffffffu, b, o);
                uint32_t na = min(a, oa);
                uint32_t nb = min(max(a, oa), min(b, ob));
                a = na; b = nb;
            }
            if (tig == 0) {
                const int row  = n0 + m * 16 + jr * 8 + gid;
                const int base = kq * 16 + wn * 2;
#pragma unroll
                for (int u = 0; u < 2; u++) {
                    uint32_t p = u ? b : a;
                    int s    = (int)(p >> 7) - (1 << 23);
                    int loc  = (int)(p & 127);
                    int ktl2 = loc >> 4, nn2 = (loc >> 3) & 1;
                    int tg2  = (loc >> 1) & 3, j2 = loc & 1;
                    int col  = (kbeg + ktl2) * 128 + (wn * 2 + nn2) * 8 +
                               tg2 * 2 + j2;
                    g_cand[row][base + u] = make_int2(s, col);
                }
            }
        }
}

// ---------------------------------------------------------------------------
// Rescore: warp per token. Top-16 of 64 candidates, exact fp32, gather winner.
// ---------------------------------------------------------------------------
__global__ __launch_bounds__(256)
void rescore_kernel(const float* __restrict__ x, const float* __restrict__ embed,
                    float* __restrict__ out) {
    const int tok  = (blockIdx.x * blockDim.x + threadIdx.x) >> 5;
    const int lane = threadIdx.x & 31;
    if (tok >= N_TOK) return;

    int2 c0 = g_cand[tok][lane];
    int2 c1 = g_cand[tok][lane + 32];
    long long p0 = ((long long)c0.x << 13) | (long long)c0.y;
    long long p1 = ((long long)c1.x << 13) | (long long)c1.y;
    if (p1 < p0) { long long tmp = p0; p0 = p1; p1 = tmp; }

    int sel[16];
#pragma unroll
    for (int r = 0; r < 16; r++) {
        long long mv = p0;
#pragma unroll
        for (int o = 16; o > 0; o >>= 1) {
            long long ov = __shfl_xor_sync(0xffffffffu, mv, o);
            if (ov < mv) mv = ov;
        }
        sel[r] = (int)(mv & 0x1FFF);
        if (p0 == mv) { p0 = p1; p1 = 0x7FFFFFFFFFFFFFFFLL; }
    }

    float xv[8];
#pragma unroll
    for (int q = 0; q < 8; q++) xv[q] = x[(size_t)tok * DIM + lane + 32 * q];

    float bv = 3.4e38f; int bk = KCODE;
#pragma unroll
    for (int r = 0; r < 16; r++) {
        const int k = sel[r];
        const float* e = embed + (size_t)k * DIM;
        float d = 0.f;
#pragma unroll
        for (int q = 0; q < 8; q++) d = fmaf(xv[q], e[lane + 32 * q], d);
#pragma unroll
        for (int o = 16; o > 0; o >>= 1) d += __shfl_xor_sync(0xffffffffu, d, o);
        float sc = fmaf(-2.f, d, g_e2[k]);
        if (sc < bv || (sc == bv && k < bk)) { bv = sc; bk = k; }
    }

    const float* e = embed + (size_t)bk * DIM;
#pragma unroll
    for (int q = 0; q < 8; q++)
        out[(size_t)tok * DIM + lane + 32 * q] = e[lane + 32 * q];
}

// ---------------------------------------------------------------------------
extern "C" void kernel_launch(void* const* d_in, const int* in_sizes, int n_in,
                              void* d_out, int out_size) {
    const float* x     = (const float*)d_in[0];
    const float* embed = (const float*)d_in[1];
    if (n_in >= 2 && in_sizes[0] < in_sizes[1]) {
        const float* tmp = x; x = embed; embed = tmp;
    }
    float* out = (float*)d_out;

    cudaFuncSetAttribute(screen_kernel, cudaFuncAttributeMaxDynamicSharedMemorySize, SMEM_TOTAL);

    equant_kernel<<<KCODE / 8, 256>>>(embed);
    screen_kernel<<<(N_TOK / BM) * KSPL, 256, SMEM_TOTAL>>>(x);
    rescore_kernel<<<N_TOK / 8, 256>>>(x, embed, out);
}